// round 14
// baseline (speedup 1.0000x reference)
#include <cuda_runtime.h>
#include <math.h>

#define BQ   8
#define CQ   96
#define LQ   4096
#define DIQ  192
#define DI2Q 384
#define DSQ  16
#define NCQ  128
#define SCHQ 32

// ---------------- scratch ----------------
static __device__ float  g_xmt [(size_t)BQ * DIQ * LQ];
static __device__ float  g_zs  [(size_t)BQ * LQ * DIQ];
static __device__ float  g_xms [(size_t)BQ * LQ * DIQ];
static __device__ float2 g_pd  [(size_t)BQ * LQ * DIQ];   // (p1=exp(delta*A0), du=delta*u)
static __device__ float  g_Bm  [(size_t)BQ * LQ * DSQ];
static __device__ float  g_Cm  [(size_t)BQ * LQ * DSQ];
// lookback state
static __device__ float  g_part[(size_t)BQ * NCQ * 17 * DIQ];
static __device__ float  g_incl[(size_t)BQ * NCQ * 16 * DIQ];
static __device__ int    g_flag[BQ * NCQ];
// prep outputs
static __device__ int    g_pat [DIQ];
static __device__ float  g_A   [DIQ * DSQ];
static __device__ float  g_invA0[DIQ];

// ---------------- fast math ----------------
__device__ __forceinline__ float fexp(float x) {
    float y = x * 1.442695041f;
    y = fminf(fmaxf(y, -126.f), 127.f);
    float n = rintf(y);
    float f = y - n;
    float p =             1.3388908e-3f;
    p = fmaf(p, f, 9.6732550e-3f);
    p = fmaf(p, f, 5.5504110e-2f);
    p = fmaf(p, f, 2.4022652e-1f);
    p = fmaf(p, f, 6.9314718e-1f);
    p = fmaf(p, f, 1.0f);
    return __int_as_float(__float_as_int(p) + (((int)n) << 23));
}

__device__ __forceinline__ float siluf(float v) { return __fdividef(v, 1.f + fexp(-v)); }

__device__ __forceinline__ unsigned f2tf(float f) {
    unsigned r; asm("cvt.rna.tf32.f32 %0, %1;" : "=r"(r) : "f"(f)); return r;
}

__device__ __forceinline__ void mma_tf32(float& c0, float& c1, float& c2, float& c3,
                                         unsigned a0, unsigned a1, unsigned a2, unsigned a3,
                                         unsigned b0, unsigned b1) {
    asm("mma.sync.aligned.m16n8k8.row.col.f32.tf32.tf32.f32 "
        "{%0,%1,%2,%3},{%4,%5,%6,%7},{%8,%9},{%0,%1,%2,%3};"
        : "+f"(c0), "+f"(c1), "+f"(c2), "+f"(c3)
        : "r"(a0), "r"(a1), "r"(a2), "r"(a3), "r"(b0), "r"(b1));
}

__device__ __forceinline__ void pw16f(float p1, float* pw) {
    float p2 = p1 * p1, p4 = p2 * p2, p8 = p4 * p4;
    pw[0] = p1;        pw[1] = p2;        pw[2] = p2 * p1;   pw[3] = p4;
    pw[4] = p4 * p1;   pw[5] = p4 * p2;   pw[6] = p4 * pw[2];pw[7] = p8;
    pw[8] = p8 * p1;   pw[9] = p8 * p2;   pw[10]= p8 * pw[2];pw[11]= p8 * p4;
    pw[12]= p8 * pw[4];pw[13]= p8 * pw[5];pw[14]= p8 * pw[6];pw[15]= p8 * p8;
}

__device__ __forceinline__ void decay16(float s, int pat, const float* a, float invA0, float* pw) {
    if (pat) {
        pw16f(s, pw);
    } else {
        float ls = __logf(s) * invA0;
        #pragma unroll
        for (int n = 0; n < DSQ; n++) pw[n] = fexp(ls * a[n]);
    }
}

__device__ __forceinline__ int ldacq(const int* p) {
    int v; asm volatile("ld.acquire.gpu.s32 %0, [%1];" : "=r"(v) : "l"(p) : "memory"); return v;
}
__device__ __forceinline__ void strel(int* p, int v) {
    asm volatile("st.release.gpu.s32 [%0], %1;" :: "l"(p), "r"(v) : "memory");
}

// ================ K1: in_proj (tf32 mma), paired xm/z tiles ================
#define K1_AS 136
#define K1_WS 100
__global__ __launch_bounds__(256) void mk_inproj(const float* __restrict__ x,
                                                 const float* __restrict__ w) {
    extern __shared__ unsigned sm_u[];
    unsigned* As = sm_u;                      // [96][136]
    unsigned* W0 = sm_u + 96 * K1_AS;         // [64][100]
    unsigned* W1 = W0 + 64 * K1_WS;           // [64][100]
    const int l0 = blockIdx.x * 128, jy = blockIdx.y * 64, b = blockIdx.z;
    const int tid = threadIdx.x;

    const float* xb = x + (size_t)b * CQ * LQ + l0;
    for (int idx = tid; idx < 96 * 32; idx += 256) {
        int c = idx >> 5, q = idx & 31;
        const float4 f4 = *(const float4*)(xb + (size_t)c * LQ + q * 4);
        unsigned* dst = &As[c * K1_AS + q * 4];
        dst[0] = f2tf(f4.x); dst[1] = f2tf(f4.y); dst[2] = f2tf(f4.z); dst[3] = f2tf(f4.w);
    }
    for (int idx = tid; idx < 64 * 24; idx += 256) {
        int j = idx / 24, q = idx - j * 24;
        const float4 f0 = *(const float4*)(w + (size_t)(jy + j) * 96 + q * 4);
        const float4 f1 = *(const float4*)(w + (size_t)(DIQ + jy + j) * 96 + q * 4);
        unsigned* d0 = &W0[j * K1_WS + q * 4];
        unsigned* d1 = &W1[j * K1_WS + q * 4];
        d0[0] = f2tf(f0.x); d0[1] = f2tf(f0.y); d0[2] = f2tf(f0.z); d0[3] = f2tf(f0.w);
        d1[0] = f2tf(f1.x); d1[1] = f2tf(f1.y); d1[2] = f2tf(f1.z); d1[3] = f2tf(f1.w);
    }
    __syncthreads();

    const int warp = tid >> 5, lane = tid & 31, g = lane >> 2, tg = lane & 3;
    const int wm = (warp & 3) * 32, wn = (warp >> 2) * 32;

    float acc[2][2][4][4];
    #pragma unroll
    for (int hf = 0; hf < 2; hf++)
        #pragma unroll
        for (int i = 0; i < 2; i++)
            #pragma unroll
            for (int jf = 0; jf < 4; jf++)
                #pragma unroll
                for (int q = 0; q < 4; q++) acc[hf][i][jf][q] = 0.f;

    #pragma unroll
    for (int ks = 0; ks < 12; ks++) {
        int k0 = ks * 8;
        unsigned a[2][4];
        #pragma unroll
        for (int i = 0; i < 2; i++) {
            int m = wm + i * 16;
            a[i][0] = As[(k0 + tg) * K1_AS + m + g];
            a[i][1] = As[(k0 + tg) * K1_AS + m + g + 8];
            a[i][2] = As[(k0 + tg + 4) * K1_AS + m + g];
            a[i][3] = As[(k0 + tg + 4) * K1_AS + m + g + 8];
        }
        #pragma unroll
        for (int jf = 0; jf < 4; jf++) {
            int n = wn + jf * 8 + g;
            unsigned b00 = W0[n * K1_WS + k0 + tg];
            unsigned b01 = W0[n * K1_WS + k0 + tg + 4];
            unsigned b10 = W1[n * K1_WS + k0 + tg];
            unsigned b11 = W1[n * K1_WS + k0 + tg + 4];
            #pragma unroll
            for (int i = 0; i < 2; i++) {
                mma_tf32(acc[0][i][jf][0], acc[0][i][jf][1], acc[0][i][jf][2], acc[0][i][jf][3],
                         a[i][0], a[i][1], a[i][2], a[i][3], b00, b01);
                mma_tf32(acc[1][i][jf][0], acc[1][i][jf][1], acc[1][i][jf][2], acc[1][i][jf][3],
                         a[i][0], a[i][1], a[i][2], a[i][3], b10, b11);
            }
        }
    }
    __syncthreads();
    float* Os = (float*)sm_u;

    #pragma unroll
    for (int i = 0; i < 2; i++)
        #pragma unroll
        for (int jf = 0; jf < 4; jf++) {
            int m = wm + i * 16 + g, n = wn + jf * 8 + tg * 2;
            Os[n * K1_AS + m]           = acc[0][i][jf][0];
            Os[(n + 1) * K1_AS + m]     = acc[0][i][jf][1];
            Os[n * K1_AS + m + 8]       = acc[0][i][jf][2];
            Os[(n + 1) * K1_AS + m + 8] = acc[0][i][jf][3];
        }
    __syncthreads();
    for (int idx = tid; idx < 64 * 128; idx += 256) {
        int n = idx >> 7, m = idx & 127;
        g_xmt[((size_t)b * DIQ + jy + n) * LQ + l0 + m] = Os[n * K1_AS + m];
    }
    __syncthreads();

    #pragma unroll
    for (int i = 0; i < 2; i++)
        #pragma unroll
        for (int jf = 0; jf < 4; jf++) {
            int m = wm + i * 16 + g, n = wn + jf * 8 + tg * 2;
            Os[m * 68 + n]           = acc[1][i][jf][0];
            Os[m * 68 + n + 1]       = acc[1][i][jf][1];
            Os[(m + 8) * 68 + n]     = acc[1][i][jf][2];
            Os[(m + 8) * 68 + n + 1] = acc[1][i][jf][3];
        }
    __syncthreads();
    for (int idx = tid; idx < 128 * 64; idx += 256) {
        int l = idx >> 6, n = idx & 63;
        g_zs[((size_t)b * LQ + l0 + l) * DIQ + jy + n] = siluf(Os[l * 68 + n]);
    }
}

// ================ K2: depthwise causal conv + silu (+ inlined prep in block 0) ====
__global__ __launch_bounds__(256) void mk_conv(const float* __restrict__ cw,
                                               const float* __restrict__ cb,
                                               const float* __restrict__ alog) {
    __shared__ float s[32][37];
    const int l0 = blockIdx.x * 32, e0 = blockIdx.y * 32, b = blockIdx.z;
    const int tx = threadIdx.x, ty = threadIdx.y;

    // prep (once, block (0,0,0)): A analysis + flag reset
    if (blockIdx.x == 0 && blockIdx.y == 0 && blockIdx.z == 0) {
        const int t = ty * 32 + tx;
        if (t < DIQ) {
            float a[DSQ];
            #pragma unroll
            for (int n = 0; n < DSQ; n++) a[n] = -fexp(alog[t * DSQ + n]);
            const float A0 = a[0];
            bool pat = true;
            #pragma unroll
            for (int n = 1; n < DSQ; n++) {
                float tgt = (float)(n + 1) * A0;
                pat = pat && (fabsf(a[n] - tgt) <= 1e-4f * (1.f + fabsf(tgt)));
            }
            g_pat[t] = pat ? 1 : 0;
            g_invA0[t] = 1.f / A0;
            #pragma unroll
            for (int n = 0; n < DSQ; n++) g_A[t * DSQ + n] = a[n];
        }
        for (int i = ty * 32 + tx; i < BQ * NCQ; i += 256) g_flag[i] = 0;
    }

    #pragma unroll
    for (int k = 0; k < 4; k++) {
        int e = ty + 8 * k;
        const float* src = g_xmt + ((size_t)b * DIQ + e0 + e) * LQ + l0;
        int l = l0 - 3 + tx;
        s[e][tx] = (l >= 0) ? src[tx - 3] : 0.f;
        if (tx < 3) s[e][tx + 32] = src[tx + 29];
    }
    __syncthreads();
    const float4 w4 = *(const float4*)(cw + (size_t)(e0 + tx) * 4);
    const float bias = cb[e0 + tx];
    float* dst = g_xms + ((size_t)b * LQ + l0) * DIQ + e0 + tx;
    #pragma unroll
    for (int k = 0; k < 4; k++) {
        int ll = ty + 8 * k;
        float v = bias + w4.x * s[tx][ll] + w4.y * s[tx][ll + 1]
                       + w4.z * s[tx][ll + 2] + w4.w * s[tx][ll + 3];
        dst[(size_t)ll * DIQ] = siluf(v);
    }
}

// ================ K3: x_proj (tf32 mma) + dt_proj + softplus + (p1,du) ================
#define K3_AS 68
#define K3_WS 68
__global__ __launch_bounds__(256) void mk_xproj(const float* __restrict__ xpw,
                                                const float* __restrict__ dtw,
                                                const float* __restrict__ dtb,
                                                const float* __restrict__ alog) {
    extern __shared__ unsigned sm_u[];
    unsigned* As = sm_u;                       // [64][68]
    unsigned* Ws = sm_u + 64 * K3_AS;          // [48][68]
    float*    Db = (float*)(Ws + 48 * K3_WS);  // [64][40]
    float*    Dt = Db + 64 * 40;               // [192][6]
    float*    Bs = Dt + 192 * 6;               // [192]
    float*    A0s = Bs + 192;                  // [192]
    const int l0 = blockIdx.x * 64, b = blockIdx.y, tid = threadIdx.x;

    for (int idx = tid; idx < 192 * 6; idx += 256) Dt[idx] = dtw[idx];
    if (tid < 192) {
        Bs[tid]  = dtb[tid];
        A0s[tid] = -fexp(alog[tid * DSQ]);
    }

    const int warp = tid >> 5, lane = tid & 31, g = lane >> 2, tg = lane & 3;
    const int wm = (warp & 3) * 16;
    const int ngrp = warp >> 2;
    const int jf0 = ngrp * 3;
    const int jcnt = 3 - ngrp;

    int al[4], aq[4];
    #pragma unroll
    for (int k = 0; k < 4; k++) { int v = tid + k * 256; al[k] = v >> 4; aq[k] = v & 15; }
    int wl[3], wq[3];
    #pragma unroll
    for (int k = 0; k < 3; k++) { int v = tid + k * 256; wl[k] = v >> 4; wq[k] = v & 15; }

    const float* xsrc = g_xms + ((size_t)b * LQ + l0) * DIQ;

    float4 ar[4], wr[3];
    #pragma unroll
    for (int k = 0; k < 4; k++)
        ar[k] = *(const float4*)(xsrc + (size_t)al[k] * DIQ + aq[k] * 4);
    #pragma unroll
    for (int k = 0; k < 3; k++)
        wr[k] = (wl[k] < 38) ? *(const float4*)(xpw + (size_t)wl[k] * DIQ + wq[k] * 4)
                             : make_float4(0.f, 0.f, 0.f, 0.f);
    #pragma unroll
    for (int k = 0; k < 4; k++) {
        unsigned* dst = &As[al[k] * K3_AS + aq[k] * 4];
        dst[0] = f2tf(ar[k].x); dst[1] = f2tf(ar[k].y); dst[2] = f2tf(ar[k].z); dst[3] = f2tf(ar[k].w);
    }
    #pragma unroll
    for (int k = 0; k < 3; k++) {
        unsigned* dst = &Ws[wl[k] * K3_WS + wq[k] * 4];
        dst[0] = f2tf(wr[k].x); dst[1] = f2tf(wr[k].y); dst[2] = f2tf(wr[k].z); dst[3] = f2tf(wr[k].w);
    }
    __syncthreads();

    float acc[3][4];
    #pragma unroll
    for (int jf = 0; jf < 3; jf++)
        #pragma unroll
        for (int q = 0; q < 4; q++) acc[jf][q] = 0.f;

    #pragma unroll
    for (int kc = 0; kc < 3; kc++) {
        if (kc < 2) {
            int e0 = (kc + 1) * 64;
            #pragma unroll
            for (int k = 0; k < 4; k++)
                ar[k] = *(const float4*)(xsrc + (size_t)al[k] * DIQ + e0 + aq[k] * 4);
            #pragma unroll
            for (int k = 0; k < 3; k++)
                wr[k] = (wl[k] < 38) ? *(const float4*)(xpw + (size_t)wl[k] * DIQ + e0 + wq[k] * 4)
                                     : make_float4(0.f, 0.f, 0.f, 0.f);
        }
        #pragma unroll
        for (int ks = 0; ks < 8; ks++) {
            int k0 = ks * 8;
            unsigned a0 = As[(wm + g) * K3_AS + k0 + tg];
            unsigned a1 = As[(wm + g + 8) * K3_AS + k0 + tg];
            unsigned a2 = As[(wm + g) * K3_AS + k0 + tg + 4];
            unsigned a3 = As[(wm + g + 8) * K3_AS + k0 + tg + 4];
            #pragma unroll
            for (int jf = 0; jf < 3; jf++) {
                int n = (jf0 + jf) * 8 + g;
                unsigned b0 = Ws[n * K3_WS + k0 + tg];
                unsigned b1 = Ws[n * K3_WS + k0 + tg + 4];
                mma_tf32(acc[jf][0], acc[jf][1], acc[jf][2], acc[jf][3],
                         a0, a1, a2, a3, b0, b1);
            }
        }
        __syncthreads();
        if (kc < 2) {
            #pragma unroll
            for (int k = 0; k < 4; k++) {
                unsigned* dst = &As[al[k] * K3_AS + aq[k] * 4];
                dst[0] = f2tf(ar[k].x); dst[1] = f2tf(ar[k].y); dst[2] = f2tf(ar[k].z); dst[3] = f2tf(ar[k].w);
            }
            #pragma unroll
            for (int k = 0; k < 3; k++) {
                unsigned* dst = &Ws[wl[k] * K3_WS + wq[k] * 4];
                dst[0] = f2tf(wr[k].x); dst[1] = f2tf(wr[k].y); dst[2] = f2tf(wr[k].z); dst[3] = f2tf(wr[k].w);
            }
            __syncthreads();
        }
    }

    #pragma unroll
    for (int jf = 0; jf < 3; jf++) {
        if (jf < jcnt) {
            int m = wm + g, n = (jf0 + jf) * 8 + tg * 2;
            Db[m * 40 + n]           = acc[jf][0];
            Db[m * 40 + n + 1]       = acc[jf][1];
            Db[(m + 8) * 40 + n]     = acc[jf][2];
            Db[(m + 8) * 40 + n + 1] = acc[jf][3];
        }
    }
    __syncthreads();

    float2* pd = g_pd + ((size_t)b * LQ + l0) * DIQ;
    {
        int l = tid / 192, ee = tid - l * 192;
        #pragma unroll 4
        for (int it = 0; it < 48; it++) {
            float d = Bs[ee];
            const float* dbl = Db + l * 40;
            #pragma unroll
            for (int r = 0; r < 6; r++) d = fmaf(dbl[r], Dt[ee * 6 + r], d);
            float t = 1.f + fexp(d);
            float delta = (d > 15.f) ? d : __logf(t);
            float A0 = A0s[ee];
            float p1 = (A0 == -1.f) ? __fdividef(1.f, t) : fexp(delta * A0);
            float u = xsrc[(size_t)l * DIQ + ee];
            float2 v; v.x = p1; v.y = delta * u;
            pd[(size_t)l * DIQ + ee] = v;
            l += 1; ee += 64;
            if (ee >= 192) { ee -= 192; l += 1; }
        }
    }
    float* bb = g_Bm + ((size_t)b * LQ + l0) * DSQ;
    float* cc = g_Cm + ((size_t)b * LQ + l0) * DSQ;
    for (int idx = tid; idx < 64 * 32; idx += 256) {
        int l = idx >> 5, n = idx & 31;
        float v = Db[l * 40 + 6 + n];
        if (n < 16) bb[(size_t)l * DSQ + n] = v;
        else        cc[(size_t)l * DSQ + (n - 16)] = v;
    }
}

// ================ K4: single-pass scan with batched decoupled lookback ================
__global__ __launch_bounds__(192) void mk_scan(const float* __restrict__ Dg) {
    __shared__ float4 sB[SCHQ][4];
    __shared__ float4 sC[SCHQ][4];
    __shared__ int sflags[4];
    const int ch = blockIdx.x, b = blockIdx.y, e = threadIdx.x;
    const size_t off = (size_t)b * LQ + (size_t)ch * SCHQ;
    if (e < SCHQ * 4) {
        ((float4*)sB)[e] = ((const float4*)(g_Bm + off * DSQ))[e];
        ((float4*)sC)[e] = ((const float4*)(g_Cm + off * DSQ))[e];
    }
    const int pat = g_pat[e];
    const float invA0 = g_invA0[e];
    float a[DSQ];
    #pragma unroll
    for (int n = 0; n < DSQ; n++) a[n] = g_A[e * DSQ + n];
    __syncthreads();

    const float2* pd = g_pd + off * DIQ + e;
    const int cidx = b * NCQ + ch;

    float h[DSQ];
    #pragma unroll
    for (int n = 0; n < DSQ; n++) h[n] = 0.f;
    float P = 1.f;

    if (ch < NCQ - 1) {
        if (pat) {
            for (int s = 0; s < SCHQ; s++) {
                float2 v = pd[(size_t)s * DIQ];
                float4 q0 = sB[s][0], q1 = sB[s][1], q2 = sB[s][2], q3 = sB[s][3];
                float Bv[16] = {q0.x,q0.y,q0.z,q0.w, q1.x,q1.y,q1.z,q1.w,
                                q2.x,q2.y,q2.z,q2.w, q3.x,q3.y,q3.z,q3.w};
                float pw[16]; pw16f(v.x, pw);
                P *= v.x;
                #pragma unroll
                for (int n = 0; n < 16; n++) h[n] = fmaf(pw[n], h[n], v.y * Bv[n]);
            }
        } else {
            for (int s = 0; s < SCHQ; s++) {
                float2 v = pd[(size_t)s * DIQ];
                float4 q0 = sB[s][0], q1 = sB[s][1], q2 = sB[s][2], q3 = sB[s][3];
                float Bv[16] = {q0.x,q0.y,q0.z,q0.w, q1.x,q1.y,q1.z,q1.w,
                                q2.x,q2.y,q2.z,q2.w, q3.x,q3.y,q3.z,q3.w};
                float delta = __logf(v.x) * invA0;
                P *= v.x;
                #pragma unroll
                for (int n = 0; n < 16; n++) h[n] = fmaf(fexp(delta * a[n]), h[n], v.y * Bv[n]);
            }
        }
        if (ch == 0) {
            float* ip = g_incl + (size_t)cidx * 16 * DIQ + e;
            #pragma unroll
            for (int n = 0; n < 16; n++) ip[n * DIQ] = h[n];
            __syncthreads();
            if (e == 0) strel(&g_flag[cidx], 2);
        } else {
            float* pp = g_part + (size_t)cidx * 17 * DIQ + e;
            #pragma unroll
            for (int n = 0; n < 16; n++) pp[n * DIQ] = h[n];
            pp[16 * DIQ] = P;
            __syncthreads();
            if (e == 0) strel(&g_flag[cidx], 1);
        }
    }

    // ---- batched lookback ----
    float hin[DSQ];
    #pragma unroll
    for (int n = 0; n < DSQ; n++) hin[n] = 0.f;
    if (ch > 0) {
        float S = 1.f;
        int j = cidx - 1;
        const int jmin = b * NCQ;
        bool done = false;
        while (!done) {
            const int cnt = min(4, j - jmin + 1);
            if (e < cnt) {
                int f;
                do { f = ldacq(&g_flag[j - e]); if (!f) __nanosleep(40); } while (!f);
                sflags[e] = f;
            }
            __syncthreads();
            int take = cnt, incl = -1;
            #pragma unroll
            for (int k = 0; k < 4; k++)
                if (k < cnt && incl < 0 && sflags[k] == 2) { incl = k; take = k + 1; }
            __syncthreads();

            if (take == 4 && incl < 0) {
                // fast path: 4 partials, load everything in one epoch
                const float* pp0 = g_part + (size_t)(j    ) * 17 * DIQ + e;
                const float* pp1 = g_part + (size_t)(j - 1) * 17 * DIQ + e;
                const float* pp2 = g_part + (size_t)(j - 2) * 17 * DIQ + e;
                const float* pp3 = g_part + (size_t)(j - 3) * 17 * DIQ + e;
                float P0 = pp0[16 * DIQ], P1 = pp1[16 * DIQ], P2 = pp2[16 * DIQ], P3 = pp3[16 * DIQ];
                float S0 = S, S1 = S0 * P0, S2 = S1 * P1, S3 = S2 * P2;
                float w0[16], w1[16], w2[16], w3[16];
                decay16(S0, pat, a, invA0, w0);
                decay16(S1, pat, a, invA0, w1);
                decay16(S2, pat, a, invA0, w2);
                decay16(S3, pat, a, invA0, w3);
                #pragma unroll
                for (int n = 0; n < 16; n++) {
                    hin[n] = fmaf(w0[n], pp0[n * DIQ], hin[n]);
                    hin[n] = fmaf(w1[n], pp1[n * DIQ], hin[n]);
                    hin[n] = fmaf(w2[n], pp2[n * DIQ], hin[n]);
                    hin[n] = fmaf(w3[n], pp3[n * DIQ], hin[n]);
                }
                S = S3 * P3;
                j -= 4;
            } else {
                for (int k = 0; k < take; k++) {
                    float pw[16]; decay16(S, pat, a, invA0, pw);
                    if (k == incl) {
                        const float* ip = g_incl + (size_t)(j - k) * 16 * DIQ + e;
                        #pragma unroll
                        for (int n = 0; n < 16; n++) hin[n] = fmaf(pw[n], ip[n * DIQ], hin[n]);
                        done = true;
                    } else {
                        const float* pp = g_part + (size_t)(j - k) * 17 * DIQ + e;
                        #pragma unroll
                        for (int n = 0; n < 16; n++) hin[n] = fmaf(pw[n], pp[n * DIQ], hin[n]);
                        S *= pp[16 * DIQ];
                    }
                }
                j -= take;
            }
        }
        if (ch < NCQ - 1) {
            float pwP[16]; decay16(P, pat, a, invA0, pwP);
            float* ip = g_incl + (size_t)cidx * 16 * DIQ + e;
            #pragma unroll
            for (int n = 0; n < 16; n++) ip[n * DIQ] = fmaf(pwP[n], hin[n], h[n]);
            __syncthreads();
            if (e == 0) strel(&g_flag[cidx], 2);
        }
    }

    // ---- phase C: replay chunk from h_in, emit y * silu(z) ----
    const float Dv = Dg[e];
    const float* up = g_xms + off * DIQ + e;
    float*       zp = g_zs  + off * DIQ + e;

    if (pat) {
        for (int s = 0; s < SCHQ; s++) {
            float2 v = pd[(size_t)s * DIQ];
            float  u = up[(size_t)s * DIQ];
            float4 q0 = sB[s][0], q1 = sB[s][1], q2 = sB[s][2], q3 = sB[s][3];
            float Bv[16] = {q0.x,q0.y,q0.z,q0.w, q1.x,q1.y,q1.z,q1.w,
                            q2.x,q2.y,q2.z,q2.w, q3.x,q3.y,q3.z,q3.w};
            float4 c0 = sC[s][0], c1 = sC[s][1], c2 = sC[s][2], c3 = sC[s][3];
            float Cv[16] = {c0.x,c0.y,c0.z,c0.w, c1.x,c1.y,c1.z,c1.w,
                            c2.x,c2.y,c2.z,c2.w, c3.x,c3.y,c3.z,c3.w};
            float pw[16]; pw16f(v.x, pw);
            float y0 = u * Dv, y1 = 0.f, y2 = 0.f, y3 = 0.f;
            #pragma unroll
            for (int n = 0; n < 16; n += 4) {
                hin[n]   = fmaf(pw[n],   hin[n],   v.y * Bv[n]);
                hin[n+1] = fmaf(pw[n+1], hin[n+1], v.y * Bv[n+1]);
                hin[n+2] = fmaf(pw[n+2], hin[n+2], v.y * Bv[n+2]);
                hin[n+3] = fmaf(pw[n+3], hin[n+3], v.y * Bv[n+3]);
                y0 = fmaf(hin[n],   Cv[n],   y0);
                y1 = fmaf(hin[n+1], Cv[n+1], y1);
                y2 = fmaf(hin[n+2], Cv[n+2], y2);
                y3 = fmaf(hin[n+3], Cv[n+3], y3);
            }
            zp[(size_t)s * DIQ] = ((y0 + y1) + (y2 + y3)) * zp[(size_t)s * DIQ];
        }
    } else {
        for (int s = 0; s < SCHQ; s++) {
            float2 v = pd[(size_t)s * DIQ];
            float  u = up[(size_t)s * DIQ];
            float4 q0 = sB[s][0], q1 = sB[s][1], q2 = sB[s][2], q3 = sB[s][3];
            float Bv[16] = {q0.x,q0.y,q0.z,q0.w, q1.x,q1.y,q1.z,q1.w,
                            q2.x,q2.y,q2.z,q2.w, q3.x,q3.y,q3.z,q3.w};
            float4 c0 = sC[s][0], c1 = sC[s][1], c2 = sC[s][2], c3 = sC[s][3];
            float Cv[16] = {c0.x,c0.y,c0.z,c0.w, c1.x,c1.y,c1.z,c1.w,
                            c2.x,c2.y,c2.z,c2.w, c3.x,c3.y,c3.z,c3.w};
            float delta = __logf(v.x) * invA0;
            float y0 = u * Dv, y1 = 0.f, y2 = 0.f, y3 = 0.f;
            #pragma unroll
            for (int n = 0; n < 16; n += 4) {
                hin[n]   = fmaf(fexp(delta * a[n]),   hin[n],   v.y * Bv[n]);
                hin[n+1] = fmaf(fexp(delta * a[n+1]), hin[n+1], v.y * Bv[n+1]);
                hin[n+2] = fmaf(fexp(delta * a[n+2]), hin[n+2], v.y * Bv[n+2]);
                hin[n+3] = fmaf(fexp(delta * a[n+3]), hin[n+3], v.y * Bv[n+3]);
                y0 = fmaf(hin[n],   Cv[n],   y0);
                y1 = fmaf(hin[n+1], Cv[n+1], y1);
                y2 = fmaf(hin[n+2], Cv[n+2], y2);
                y3 = fmaf(hin[n+3], Cv[n+3], y3);
            }
            zp[(size_t)s * DIQ] = ((y0 + y1) + (y2 + y3)) * zp[(size_t)s * DIQ];
        }
    }
}

// ================ K7: out_proj (tf32 mma) + LayerNorm + transpose ================
#define K7_AS 68
#define K7_WS 68
__global__ __launch_bounds__(256) void mk_outln(const float* __restrict__ ow,
                                                const float* __restrict__ gam,
                                                const float* __restrict__ bet,
                                                float* __restrict__ out) {
    extern __shared__ unsigned sm_u[];
    unsigned* As = sm_u;
    unsigned* Ws = sm_u + 128 * K7_AS;
    float* Os = (float*)sm_u;
    float* Mu = (float*)(sm_u + 128 * K7_AS + 96 * K7_WS);
    float* Rs = Mu + 128;
    const int l0 = blockIdx.x * 128, b = blockIdx.y, tid = threadIdx.x;

    const int warp = tid >> 5, lane = tid & 31, g = lane >> 2, tg = lane & 3;
    const int wm = (warp & 3) * 32, wn = (warp >> 2) * 48;

    float acc[2][6][4];
    #pragma unroll
    for (int i = 0; i < 2; i++)
        #pragma unroll
        for (int jf = 0; jf < 6; jf++)
            #pragma unroll
            for (int q = 0; q < 4; q++) acc[i][jf][q] = 0.f;

    const float* ysrc = g_zs + ((size_t)b * LQ + l0) * DIQ;
    for (int kc = 0; kc < 3; kc++) {
        int e0 = kc * 64;
        __syncthreads();
        for (int v = tid; v < 128 * 16; v += 256) {
            int l = v >> 4, q = v & 15;
            const float4 f4 = *(const float4*)(ysrc + (size_t)l * DIQ + e0 + q * 4);
            unsigned* dst = &As[l * K7_AS + q * 4];
            dst[0] = f2tf(f4.x); dst[1] = f2tf(f4.y); dst[2] = f2tf(f4.z); dst[3] = f2tf(f4.w);
        }
        for (int v = tid; v < 96 * 16; v += 256) {
            int o = v >> 4, q = v & 15;
            const float4 f4 = *(const float4*)(ow + (size_t)o * DIQ + e0 + q * 4);
            unsigned* dst = &Ws[o * K7_WS + q * 4];
            dst[0] = f2tf(f4.x); dst[1] = f2tf(f4.y); dst[2] = f2tf(f4.z); dst[3] = f2tf(f4.w);
        }
        __syncthreads();
        #pragma unroll
        for (int ks = 0; ks < 8; ks++) {
            int k0 = ks * 8;
            unsigned a[2][4];
            #pragma unroll
            for (int i = 0; i < 2; i++) {
                int m = wm + i * 16;
                a[i][0] = As[(m + g) * K7_AS + k0 + tg];
                a[i][1] = As[(m + g + 8) * K7_AS + k0 + tg];
                a[i][2] = As[(m + g) * K7_AS + k0 + tg + 4];
                a[i][3] = As[(m + g + 8) * K7_AS + k0 + tg + 4];
            }
            #pragma unroll
            for (int jf = 0; jf < 6; jf++) {
                int n = wn + jf * 8 + g;
                unsigned b0 = Ws[n * K7_WS + k0 + tg];
                unsigned b1 = Ws[n * K7_WS + k0 + tg + 4];
                #pragma unroll
                for (int i = 0; i < 2; i++)
                    mma_tf32(acc[i][jf][0], acc[i][jf][1], acc[i][jf][2], acc[i][jf][3],
                             a[i][0], a[i][1], a[i][2], a[i][3], b0, b1);
            }
        }
    }
    __syncthreads();
    #pragma unroll
    for (int i = 0; i < 2; i++)
        #pragma unroll
        for (int jf = 0; jf < 6; jf++) {
            int m = wm + i * 16 + g, n = wn + jf * 8 + tg * 2;
            Os[m * 100 + n]           = acc[i][jf][0];
            Os[m * 100 + n + 1]       = acc[i][jf][1];
            Os[(m + 8) * 100 + n]     = acc[i][jf][2];
            Os[(m + 8) * 100 + n + 1] = acc[i][jf][3];
        }
    __syncthreads();

    if (tid < 128) {
        float s = 0.f;
        for (int o = 0; o < 96; o++) s += Os[tid * 100 + o];
        float mu = s * (1.f / 96.f);
        float v = 0.f;
        for (int o = 0; o < 96; o++) { float d = Os[tid * 100 + o] - mu; v = fmaf(d, d, v); }
        Mu[tid] = mu;
        Rs[tid] = rsqrtf(v * (1.f / 96.f) + 1e-5f);
    }
    __syncthreads();

    float* ob = out + (size_t)b * CQ * LQ + l0;
    for (int idx = tid; idx < 96 * 128; idx += 256) {
        int o = idx >> 7, l = idx & 127;
        ob[(size_t)o * LQ + l] = (Os[l * 100 + o] - Mu[l]) * Rs[l] * gam[o] + bet[o];
    }
}

// ================ launch ================
extern "C" void kernel_launch(void* const* d_in, const int* in_sizes, int n_in,
                              void* d_out, int out_size) {
    const float* x    = (const float*)d_in[0];
    const float* inw  = (const float*)d_in[1];
    const float* cw   = (const float*)d_in[2];
    const float* cb   = (const float*)d_in[3];
    const float* xpw  = (const float*)d_in[4];
    const float* dtw  = (const float*)d_in[5];
    const float* dtb  = (const float*)d_in[6];
    const float* alog = (const float*)d_in[7];
    const float* Dg   = (const float*)d_in[8];
    const float* ow   = (const float*)d_in[9];
    const float* gam  = (const float*)d_in[10];
    const float* bet  = (const float*)d_in[11];
    float* out = (float*)d_out;

    const int SMEM1 = (96 * K1_AS + 128 * K1_WS) * 4;
    const int SMEM3 = (64 * K3_AS + 48 * K3_WS + 64 * 40 + 192 * 6 + 384) * 4;
    const int SMEM7 = (128 * K7_AS + 96 * K7_WS + 256) * 4;

    cudaFuncSetAttribute(mk_inproj, cudaFuncAttributeMaxDynamicSharedMemorySize, SMEM1);
    cudaFuncSetAttribute(mk_xproj,  cudaFuncAttributeMaxDynamicSharedMemorySize, SMEM3);
    cudaFuncSetAttribute(mk_outln,  cudaFuncAttributeMaxDynamicSharedMemorySize, SMEM7);

    mk_inproj<<<dim3(LQ / 128, DIQ / 64, BQ), 256, SMEM1>>>(x, inw);
    mk_conv  <<<dim3(LQ / 32, DIQ / 32, BQ), dim3(32, 8)>>>(cw, cb, alog);
    mk_xproj <<<dim3(LQ / 64, BQ), 256, SMEM3>>>(xpw, dtw, dtb, alog);
    mk_scan  <<<dim3(NCQ, BQ), DIQ>>>(Dg);
    mk_outln <<<dim3(LQ / 128, BQ), 256, SMEM7>>>(ow, gam, bet, out);
}

// round 15
// speedup vs baseline: 1.1934x; 1.1934x over previous
#include <cuda_runtime.h>
#include <math.h>

#define BQ   8
#define CQ   96
#define LQ   4096
#define DIQ  192
#define DI2Q 384
#define DSQ  16
#define NCQ  128
#define SCHQ 32

// ---------------- scratch ----------------
static __device__ float  g_xmt [(size_t)BQ * DIQ * LQ];
static __device__ float  g_zs  [(size_t)BQ * LQ * DIQ];
static __device__ float  g_xms [(size_t)BQ * LQ * DIQ];
static __device__ float2 g_pd  [(size_t)BQ * LQ * DIQ];   // (p1=exp(delta*A0), du=delta*u)
static __device__ float  g_Bm  [(size_t)BQ * LQ * DSQ];
static __device__ float  g_Cm  [(size_t)BQ * LQ * DSQ];
// lookback state
static __device__ float  g_part[(size_t)BQ * NCQ * 17 * DIQ];
static __device__ float  g_incl[(size_t)BQ * NCQ * 16 * DIQ];
static __device__ int    g_flag[BQ * NCQ];
// prep outputs
static __device__ int    g_pat [DIQ];
static __device__ float  g_A   [DIQ * DSQ];
static __device__ float  g_invA0[DIQ];

// ---------------- fast math ----------------
__device__ __forceinline__ float fexp(float x) {
    float y = x * 1.442695041f;
    y = fminf(fmaxf(y, -126.f), 127.f);
    float n = rintf(y);
    float f = y - n;
    float p =             1.3388908e-3f;
    p = fmaf(p, f, 9.6732550e-3f);
    p = fmaf(p, f, 5.5504110e-2f);
    p = fmaf(p, f, 2.4022652e-1f);
    p = fmaf(p, f, 6.9314718e-1f);
    p = fmaf(p, f, 1.0f);
    return __int_as_float(__float_as_int(p) + (((int)n) << 23));
}

__device__ __forceinline__ float siluf(float v) { return __fdividef(v, 1.f + fexp(-v)); }

__device__ __forceinline__ unsigned f2tf(float f) {
    unsigned r; asm("cvt.rna.tf32.f32 %0, %1;" : "=r"(r) : "f"(f)); return r;
}

__device__ __forceinline__ void mma_tf32(float& c0, float& c1, float& c2, float& c3,
                                         unsigned a0, unsigned a1, unsigned a2, unsigned a3,
                                         unsigned b0, unsigned b1) {
    asm("mma.sync.aligned.m16n8k8.row.col.f32.tf32.tf32.f32 "
        "{%0,%1,%2,%3},{%4,%5,%6,%7},{%8,%9},{%0,%1,%2,%3};"
        : "+f"(c0), "+f"(c1), "+f"(c2), "+f"(c3)
        : "r"(a0), "r"(a1), "r"(a2), "r"(a3), "r"(b0), "r"(b1));
}

__device__ __forceinline__ void pw16f(float p1, float* pw) {
    float p2 = p1 * p1, p4 = p2 * p2, p8 = p4 * p4;
    pw[0] = p1;        pw[1] = p2;        pw[2] = p2 * p1;   pw[3] = p4;
    pw[4] = p4 * p1;   pw[5] = p4 * p2;   pw[6] = p4 * pw[2];pw[7] = p8;
    pw[8] = p8 * p1;   pw[9] = p8 * p2;   pw[10]= p8 * pw[2];pw[11]= p8 * p4;
    pw[12]= p8 * pw[4];pw[13]= p8 * pw[5];pw[14]= p8 * pw[6];pw[15]= p8 * p8;
}

__device__ __forceinline__ void decay16(float s, int pat, const float* a, float invA0, float* pw) {
    if (pat) {
        pw16f(s, pw);
    } else {
        float ls = __logf(s) * invA0;
        #pragma unroll
        for (int n = 0; n < DSQ; n++) pw[n] = fexp(ls * a[n]);
    }
}

__device__ __forceinline__ int ldacq(const int* p) {
    int v; asm volatile("ld.acquire.gpu.s32 %0, [%1];" : "=r"(v) : "l"(p) : "memory"); return v;
}
__device__ __forceinline__ void strel(int* p, int v) {
    asm volatile("st.release.gpu.s32 [%0], %1;" :: "l"(p), "r"(v) : "memory");
}

// ================ K1: in_proj (tf32 mma), paired xm/z tiles ================
#define K1_AS 136
#define K1_WS 100
__global__ __launch_bounds__(256) void mk_inproj(const float* __restrict__ x,
                                                 const float* __restrict__ w) {
    extern __shared__ unsigned sm_u[];
    unsigned* As = sm_u;                      // [96][136]
    unsigned* W0 = sm_u + 96 * K1_AS;         // [64][100]
    unsigned* W1 = W0 + 64 * K1_WS;           // [64][100]
    const int l0 = blockIdx.x * 128, jy = blockIdx.y * 64, b = blockIdx.z;
    const int tid = threadIdx.x;

    const float* xb = x + (size_t)b * CQ * LQ + l0;
    for (int idx = tid; idx < 96 * 32; idx += 256) {
        int c = idx >> 5, q = idx & 31;
        const float4 f4 = *(const float4*)(xb + (size_t)c * LQ + q * 4);
        unsigned* dst = &As[c * K1_AS + q * 4];
        dst[0] = f2tf(f4.x); dst[1] = f2tf(f4.y); dst[2] = f2tf(f4.z); dst[3] = f2tf(f4.w);
    }
    for (int idx = tid; idx < 64 * 24; idx += 256) {
        int j = idx / 24, q = idx - j * 24;
        const float4 f0 = *(const float4*)(w + (size_t)(jy + j) * 96 + q * 4);
        const float4 f1 = *(const float4*)(w + (size_t)(DIQ + jy + j) * 96 + q * 4);
        unsigned* d0 = &W0[j * K1_WS + q * 4];
        unsigned* d1 = &W1[j * K1_WS + q * 4];
        d0[0] = f2tf(f0.x); d0[1] = f2tf(f0.y); d0[2] = f2tf(f0.z); d0[3] = f2tf(f0.w);
        d1[0] = f2tf(f1.x); d1[1] = f2tf(f1.y); d1[2] = f2tf(f1.z); d1[3] = f2tf(f1.w);
    }
    __syncthreads();

    const int warp = tid >> 5, lane = tid & 31, g = lane >> 2, tg = lane & 3;
    const int wm = (warp & 3) * 32, wn = (warp >> 2) * 32;

    float acc[2][2][4][4];
    #pragma unroll
    for (int hf = 0; hf < 2; hf++)
        #pragma unroll
        for (int i = 0; i < 2; i++)
            #pragma unroll
            for (int jf = 0; jf < 4; jf++)
                #pragma unroll
                for (int q = 0; q < 4; q++) acc[hf][i][jf][q] = 0.f;

    #pragma unroll
    for (int ks = 0; ks < 12; ks++) {
        int k0 = ks * 8;
        unsigned a[2][4];
        #pragma unroll
        for (int i = 0; i < 2; i++) {
            int m = wm + i * 16;
            a[i][0] = As[(k0 + tg) * K1_AS + m + g];
            a[i][1] = As[(k0 + tg) * K1_AS + m + g + 8];
            a[i][2] = As[(k0 + tg + 4) * K1_AS + m + g];
            a[i][3] = As[(k0 + tg + 4) * K1_AS + m + g + 8];
        }
        #pragma unroll
        for (int jf = 0; jf < 4; jf++) {
            int n = wn + jf * 8 + g;
            unsigned b00 = W0[n * K1_WS + k0 + tg];
            unsigned b01 = W0[n * K1_WS + k0 + tg + 4];
            unsigned b10 = W1[n * K1_WS + k0 + tg];
            unsigned b11 = W1[n * K1_WS + k0 + tg + 4];
            #pragma unroll
            for (int i = 0; i < 2; i++) {
                mma_tf32(acc[0][i][jf][0], acc[0][i][jf][1], acc[0][i][jf][2], acc[0][i][jf][3],
                         a[i][0], a[i][1], a[i][2], a[i][3], b00, b01);
                mma_tf32(acc[1][i][jf][0], acc[1][i][jf][1], acc[1][i][jf][2], acc[1][i][jf][3],
                         a[i][0], a[i][1], a[i][2], a[i][3], b10, b11);
            }
        }
    }
    __syncthreads();
    float* Os = (float*)sm_u;

    #pragma unroll
    for (int i = 0; i < 2; i++)
        #pragma unroll
        for (int jf = 0; jf < 4; jf++) {
            int m = wm + i * 16 + g, n = wn + jf * 8 + tg * 2;
            Os[n * K1_AS + m]           = acc[0][i][jf][0];
            Os[(n + 1) * K1_AS + m]     = acc[0][i][jf][1];
            Os[n * K1_AS + m + 8]       = acc[0][i][jf][2];
            Os[(n + 1) * K1_AS + m + 8] = acc[0][i][jf][3];
        }
    __syncthreads();
    for (int idx = tid; idx < 64 * 128; idx += 256) {
        int n = idx >> 7, m = idx & 127;
        g_xmt[((size_t)b * DIQ + jy + n) * LQ + l0 + m] = Os[n * K1_AS + m];
    }
    __syncthreads();

    #pragma unroll
    for (int i = 0; i < 2; i++)
        #pragma unroll
        for (int jf = 0; jf < 4; jf++) {
            int m = wm + i * 16 + g, n = wn + jf * 8 + tg * 2;
            Os[m * 68 + n]           = acc[1][i][jf][0];
            Os[m * 68 + n + 1]       = acc[1][i][jf][1];
            Os[(m + 8) * 68 + n]     = acc[1][i][jf][2];
            Os[(m + 8) * 68 + n + 1] = acc[1][i][jf][3];
        }
    __syncthreads();
    for (int idx = tid; idx < 128 * 64; idx += 256) {
        int l = idx >> 6, n = idx & 63;
        g_zs[((size_t)b * LQ + l0 + l) * DIQ + jy + n] = siluf(Os[l * 68 + n]);
    }
}

// ================ K2: depthwise causal conv + silu (+ inlined prep in block 0) ====
__global__ __launch_bounds__(256) void mk_conv(const float* __restrict__ cw,
                                               const float* __restrict__ cb,
                                               const float* __restrict__ alog) {
    __shared__ float s[32][37];
    const int l0 = blockIdx.x * 32, e0 = blockIdx.y * 32, b = blockIdx.z;
    const int tx = threadIdx.x, ty = threadIdx.y;

    if (blockIdx.x == 0 && blockIdx.y == 0 && blockIdx.z == 0) {
        const int t = ty * 32 + tx;
        if (t < DIQ) {
            float a[DSQ];
            #pragma unroll
            for (int n = 0; n < DSQ; n++) a[n] = -fexp(alog[t * DSQ + n]);
            const float A0 = a[0];
            bool pat = true;
            #pragma unroll
            for (int n = 1; n < DSQ; n++) {
                float tgt = (float)(n + 1) * A0;
                pat = pat && (fabsf(a[n] - tgt) <= 1e-4f * (1.f + fabsf(tgt)));
            }
            g_pat[t] = pat ? 1 : 0;
            g_invA0[t] = 1.f / A0;
            #pragma unroll
            for (int n = 0; n < DSQ; n++) g_A[t * DSQ + n] = a[n];
        }
        for (int i = ty * 32 + tx; i < BQ * NCQ; i += 256) g_flag[i] = 0;
    }

    #pragma unroll
    for (int k = 0; k < 4; k++) {
        int e = ty + 8 * k;
        const float* src = g_xmt + ((size_t)b * DIQ + e0 + e) * LQ + l0;
        int l = l0 - 3 + tx;
        s[e][tx] = (l >= 0) ? src[tx - 3] : 0.f;
        if (tx < 3) s[e][tx + 32] = src[tx + 29];
    }
    __syncthreads();
    const float4 w4 = *(const float4*)(cw + (size_t)(e0 + tx) * 4);
    const float bias = cb[e0 + tx];
    float* dst = g_xms + ((size_t)b * LQ + l0) * DIQ + e0 + tx;
    #pragma unroll
    for (int k = 0; k < 4; k++) {
        int ll = ty + 8 * k;
        float v = bias + w4.x * s[tx][ll] + w4.y * s[tx][ll + 1]
                       + w4.z * s[tx][ll + 2] + w4.w * s[tx][ll + 3];
        dst[(size_t)ll * DIQ] = siluf(v);
    }
}

// ================ K3: x_proj (tf32 mma) + dt_proj + softplus + (p1,du) ================
#define K3_AS 68
#define K3_WS 68
__global__ __launch_bounds__(256) void mk_xproj(const float* __restrict__ xpw,
                                                const float* __restrict__ dtw,
                                                const float* __restrict__ dtb,
                                                const float* __restrict__ alog) {
    extern __shared__ unsigned sm_u[];
    unsigned* As = sm_u;                       // [64][68]
    unsigned* Ws = sm_u + 64 * K3_AS;          // [48][68]
    float*    Db = (float*)(Ws + 48 * K3_WS);  // [64][40]
    float*    Dt = Db + 64 * 40;               // [192][6]
    float*    Bs = Dt + 192 * 6;               // [192]
    float*    A0s = Bs + 192;                  // [192]
    const int l0 = blockIdx.x * 64, b = blockIdx.y, tid = threadIdx.x;

    for (int idx = tid; idx < 192 * 6; idx += 256) Dt[idx] = dtw[idx];
    if (tid < 192) {
        Bs[tid]  = dtb[tid];
        A0s[tid] = -fexp(alog[tid * DSQ]);
    }

    const int warp = tid >> 5, lane = tid & 31, g = lane >> 2, tg = lane & 3;
    const int wm = (warp & 3) * 16;
    const int ngrp = warp >> 2;
    const int jf0 = ngrp * 3;
    const int jcnt = 3 - ngrp;

    int al[4], aq[4];
    #pragma unroll
    for (int k = 0; k < 4; k++) { int v = tid + k * 256; al[k] = v >> 4; aq[k] = v & 15; }
    int wl[3], wq[3];
    #pragma unroll
    for (int k = 0; k < 3; k++) { int v = tid + k * 256; wl[k] = v >> 4; wq[k] = v & 15; }

    const float* xsrc = g_xms + ((size_t)b * LQ + l0) * DIQ;

    float4 ar[4], wr[3];
    #pragma unroll
    for (int k = 0; k < 4; k++)
        ar[k] = *(const float4*)(xsrc + (size_t)al[k] * DIQ + aq[k] * 4);
    #pragma unroll
    for (int k = 0; k < 3; k++)
        wr[k] = (wl[k] < 38) ? *(const float4*)(xpw + (size_t)wl[k] * DIQ + wq[k] * 4)
                             : make_float4(0.f, 0.f, 0.f, 0.f);
    #pragma unroll
    for (int k = 0; k < 4; k++) {
        unsigned* dst = &As[al[k] * K3_AS + aq[k] * 4];
        dst[0] = f2tf(ar[k].x); dst[1] = f2tf(ar[k].y); dst[2] = f2tf(ar[k].z); dst[3] = f2tf(ar[k].w);
    }
    #pragma unroll
    for (int k = 0; k < 3; k++) {
        unsigned* dst = &Ws[wl[k] * K3_WS + wq[k] * 4];
        dst[0] = f2tf(wr[k].x); dst[1] = f2tf(wr[k].y); dst[2] = f2tf(wr[k].z); dst[3] = f2tf(wr[k].w);
    }
    __syncthreads();

    float acc[3][4];
    #pragma unroll
    for (int jf = 0; jf < 3; jf++)
        #pragma unroll
        for (int q = 0; q < 4; q++) acc[jf][q] = 0.f;

    #pragma unroll
    for (int kc = 0; kc < 3; kc++) {
        if (kc < 2) {
            int e0 = (kc + 1) * 64;
            #pragma unroll
            for (int k = 0; k < 4; k++)
                ar[k] = *(const float4*)(xsrc + (size_t)al[k] * DIQ + e0 + aq[k] * 4);
            #pragma unroll
            for (int k = 0; k < 3; k++)
                wr[k] = (wl[k] < 38) ? *(const float4*)(xpw + (size_t)wl[k] * DIQ + e0 + wq[k] * 4)
                                     : make_float4(0.f, 0.f, 0.f, 0.f);
        }
        #pragma unroll
        for (int ks = 0; ks < 8; ks++) {
            int k0 = ks * 8;
            unsigned a0 = As[(wm + g) * K3_AS + k0 + tg];
            unsigned a1 = As[(wm + g + 8) * K3_AS + k0 + tg];
            unsigned a2 = As[(wm + g) * K3_AS + k0 + tg + 4];
            unsigned a3 = As[(wm + g + 8) * K3_AS + k0 + tg + 4];
            #pragma unroll
            for (int jf = 0; jf < 3; jf++) {
                int n = (jf0 + jf) * 8 + g;
                unsigned b0 = Ws[n * K3_WS + k0 + tg];
                unsigned b1 = Ws[n * K3_WS + k0 + tg + 4];
                mma_tf32(acc[jf][0], acc[jf][1], acc[jf][2], acc[jf][3],
                         a0, a1, a2, a3, b0, b1);
            }
        }
        __syncthreads();
        if (kc < 2) {
            #pragma unroll
            for (int k = 0; k < 4; k++) {
                unsigned* dst = &As[al[k] * K3_AS + aq[k] * 4];
                dst[0] = f2tf(ar[k].x); dst[1] = f2tf(ar[k].y); dst[2] = f2tf(ar[k].z); dst[3] = f2tf(ar[k].w);
            }
            #pragma unroll
            for (int k = 0; k < 3; k++) {
                unsigned* dst = &Ws[wl[k] * K3_WS + wq[k] * 4];
                dst[0] = f2tf(wr[k].x); dst[1] = f2tf(wr[k].y); dst[2] = f2tf(wr[k].z); dst[3] = f2tf(wr[k].w);
            }
            __syncthreads();
        }
    }

    #pragma unroll
    for (int jf = 0; jf < 3; jf++) {
        if (jf < jcnt) {
            int m = wm + g, n = (jf0 + jf) * 8 + tg * 2;
            Db[m * 40 + n]           = acc[jf][0];
            Db[m * 40 + n + 1]       = acc[jf][1];
            Db[(m + 8) * 40 + n]     = acc[jf][2];
            Db[(m + 8) * 40 + n + 1] = acc[jf][3];
        }
    }
    __syncthreads();

    float2* pd = g_pd + ((size_t)b * LQ + l0) * DIQ;
    {
        int l = tid / 192, ee = tid - l * 192;
        #pragma unroll 4
        for (int it = 0; it < 48; it++) {
            float d = Bs[ee];
            const float* dbl = Db + l * 40;
            #pragma unroll
            for (int r = 0; r < 6; r++) d = fmaf(dbl[r], Dt[ee * 6 + r], d);
            float t = 1.f + fexp(d);
            float delta = (d > 15.f) ? d : __logf(t);
            float A0 = A0s[ee];
            float p1 = (A0 == -1.f) ? __fdividef(1.f, t) : fexp(delta * A0);
            float u = xsrc[(size_t)l * DIQ + ee];
            float2 v; v.x = p1; v.y = delta * u;
            pd[(size_t)l * DIQ + ee] = v;
            l += 1; ee += 64;
            if (ee >= 192) { ee -= 192; l += 1; }
        }
    }
    float* bb = g_Bm + ((size_t)b * LQ + l0) * DSQ;
    float* cc = g_Cm + ((size_t)b * LQ + l0) * DSQ;
    for (int idx = tid; idx < 64 * 32; idx += 256) {
        int l = idx >> 5, n = idx & 31;
        float v = Db[l * 40 + 6 + n];
        if (n < 16) bb[(size_t)l * DSQ + n] = v;
        else        cc[(size_t)l * DSQ + (n - 16)] = v;
    }
}

// ================ K4: single-pass scan with decoupled lookback ================
__global__ __launch_bounds__(192) void mk_scan(const float* __restrict__ Dg) {
    __shared__ float4 sB[SCHQ][4];
    __shared__ float4 sC[SCHQ][4];
    __shared__ int sflag;
    const int ch = blockIdx.x, b = blockIdx.y, e = threadIdx.x;
    const size_t off = (size_t)b * LQ + (size_t)ch * SCHQ;
    if (e < SCHQ * 4) {
        ((float4*)sB)[e] = ((const float4*)(g_Bm + off * DSQ))[e];
        ((float4*)sC)[e] = ((const float4*)(g_Cm + off * DSQ))[e];
    }
    const int pat = g_pat[e];
    const float invA0 = g_invA0[e];
    float a[DSQ];
    #pragma unroll
    for (int n = 0; n < DSQ; n++) a[n] = g_A[e * DSQ + n];
    __syncthreads();

    const float2* pd = g_pd + off * DIQ + e;
    const int cidx = b * NCQ + ch;

    float h[DSQ];
    #pragma unroll
    for (int n = 0; n < DSQ; n++) h[n] = 0.f;
    float P = 1.f;

    if (ch < NCQ - 1) {
        if (pat) {
            for (int s = 0; s < SCHQ; s++) {
                float2 v = pd[(size_t)s * DIQ];
                float4 q0 = sB[s][0], q1 = sB[s][1], q2 = sB[s][2], q3 = sB[s][3];
                float Bv[16] = {q0.x,q0.y,q0.z,q0.w, q1.x,q1.y,q1.z,q1.w,
                                q2.x,q2.y,q2.z,q2.w, q3.x,q3.y,q3.z,q3.w};
                float pw[16]; pw16f(v.x, pw);
                P *= v.x;
                #pragma unroll
                for (int n = 0; n < 16; n++) h[n] = fmaf(pw[n], h[n], v.y * Bv[n]);
            }
        } else {
            for (int s = 0; s < SCHQ; s++) {
                float2 v = pd[(size_t)s * DIQ];
                float4 q0 = sB[s][0], q1 = sB[s][1], q2 = sB[s][2], q3 = sB[s][3];
                float Bv[16] = {q0.x,q0.y,q0.z,q0.w, q1.x,q1.y,q1.z,q1.w,
                                q2.x,q2.y,q2.z,q2.w, q3.x,q3.y,q3.z,q3.w};
                float delta = __logf(v.x) * invA0;
                P *= v.x;
                #pragma unroll
                for (int n = 0; n < 16; n++) h[n] = fmaf(fexp(delta * a[n]), h[n], v.y * Bv[n]);
            }
        }
        if (ch == 0) {
            float* ip = g_incl + (size_t)cidx * 16 * DIQ + e;
            #pragma unroll
            for (int n = 0; n < 16; n++) ip[n * DIQ] = h[n];
            __syncthreads();
            if (e == 0) strel(&g_flag[cidx], 2);
        } else {
            float* pp = g_part + (size_t)cidx * 17 * DIQ + e;
            #pragma unroll
            for (int n = 0; n < 16; n++) pp[n * DIQ] = h[n];
            pp[16 * DIQ] = P;
            __syncthreads();
            if (e == 0) strel(&g_flag[cidx], 1);
        }
    }

    float hin[DSQ];
    #pragma unroll
    for (int n = 0; n < DSQ; n++) hin[n] = 0.f;
    if (ch > 0) {
        float S = 1.f;
        int j = cidx - 1;
        for (;;) {
            if (e == 0) {
                int f;
                do { f = ldacq(&g_flag[j]); if (!f) __nanosleep(40); } while (!f);
                sflag = f;
            }
            __syncthreads();
            int f = sflag;
            __syncthreads();
            float pw[16]; decay16(S, pat, a, invA0, pw);
            if (f == 2) {
                const float* ip = g_incl + (size_t)j * 16 * DIQ + e;
                #pragma unroll
                for (int n = 0; n < 16; n++) hin[n] = fmaf(pw[n], ip[n * DIQ], hin[n]);
                break;
            } else {
                const float* pp = g_part + (size_t)j * 17 * DIQ + e;
                #pragma unroll
                for (int n = 0; n < 16; n++) hin[n] = fmaf(pw[n], pp[n * DIQ], hin[n]);
                S *= pp[16 * DIQ];
                j--;
            }
        }
        if (ch < NCQ - 1) {
            float pwP[16]; decay16(P, pat, a, invA0, pwP);
            float* ip = g_incl + (size_t)cidx * 16 * DIQ + e;
            #pragma unroll
            for (int n = 0; n < 16; n++) ip[n * DIQ] = fmaf(pwP[n], hin[n], h[n]);
            __syncthreads();
            if (e == 0) strel(&g_flag[cidx], 2);
        }
    }

    const float Dv = Dg[e];
    const float* up = g_xms + off * DIQ + e;
    float*       zp = g_zs  + off * DIQ + e;

    if (pat) {
        for (int s = 0; s < SCHQ; s++) {
            float2 v = pd[(size_t)s * DIQ];
            float  u = up[(size_t)s * DIQ];
            float4 q0 = sB[s][0], q1 = sB[s][1], q2 = sB[s][2], q3 = sB[s][3];
            float Bv[16] = {q0.x,q0.y,q0.z,q0.w, q1.x,q1.y,q1.z,q1.w,
                            q2.x,q2.y,q2.z,q2.w, q3.x,q3.y,q3.z,q3.w};
            float4 c0 = sC[s][0], c1 = sC[s][1], c2 = sC[s][2], c3 = sC[s][3];
            float Cv[16] = {c0.x,c0.y,c0.z,c0.w, c1.x,c1.y,c1.z,c1.w,
                            c2.x,c2.y,c2.z,c2.w, c3.x,c3.y,c3.z,c3.w};
            float pw[16]; pw16f(v.x, pw);
            float y0 = u * Dv, y1 = 0.f, y2 = 0.f, y3 = 0.f;
            #pragma unroll
            for (int n = 0; n < 16; n += 4) {
                hin[n]   = fmaf(pw[n],   hin[n],   v.y * Bv[n]);
                hin[n+1] = fmaf(pw[n+1], hin[n+1], v.y * Bv[n+1]);
                hin[n+2] = fmaf(pw[n+2], hin[n+2], v.y * Bv[n+2]);
                hin[n+3] = fmaf(pw[n+3], hin[n+3], v.y * Bv[n+3]);
                y0 = fmaf(hin[n],   Cv[n],   y0);
                y1 = fmaf(hin[n+1], Cv[n+1], y1);
                y2 = fmaf(hin[n+2], Cv[n+2], y2);
                y3 = fmaf(hin[n+3], Cv[n+3], y3);
            }
            zp[(size_t)s * DIQ] = ((y0 + y1) + (y2 + y3)) * zp[(size_t)s * DIQ];
        }
    } else {
        for (int s = 0; s < SCHQ; s++) {
            float2 v = pd[(size_t)s * DIQ];
            float  u = up[(size_t)s * DIQ];
            float4 q0 = sB[s][0], q1 = sB[s][1], q2 = sB[s][2], q3 = sB[s][3];
            float Bv[16] = {q0.x,q0.y,q0.z,q0.w, q1.x,q1.y,q1.z,q1.w,
                            q2.x,q2.y,q2.z,q2.w, q3.x,q3.y,q3.z,q3.w};
            float4 c0 = sC[s][0], c1 = sC[s][1], c2 = sC[s][2], c3 = sC[s][3];
            float Cv[16] = {c0.x,c0.y,c0.z,c0.w, c1.x,c1.y,c1.z,c1.w,
                            c2.x,c2.y,c2.z,c2.w, c3.x,c3.y,c3.z,c3.w};
            float delta = __logf(v.x) * invA0;
            float y0 = u * Dv, y1 = 0.f, y2 = 0.f, y3 = 0.f;
            #pragma unroll
            for (int n = 0; n < 16; n += 4) {
                hin[n]   = fmaf(fexp(delta * a[n]),   hin[n],   v.y * Bv[n]);
                hin[n+1] = fmaf(fexp(delta * a[n+1]), hin[n+1], v.y * Bv[n+1]);
                hin[n+2] = fmaf(fexp(delta * a[n+2]), hin[n+2], v.y * Bv[n+2]);
                hin[n+3] = fmaf(fexp(delta * a[n+3]), hin[n+3], v.y * Bv[n+3]);
                y0 = fmaf(hin[n],   Cv[n],   y0);
                y1 = fmaf(hin[n+1], Cv[n+1], y1);
                y2 = fmaf(hin[n+2], Cv[n+2], y2);
                y3 = fmaf(hin[n+3], Cv[n+3], y3);
            }
            zp[(size_t)s * DIQ] = ((y0 + y1) + (y2 + y3)) * zp[(size_t)s * DIQ];
        }
    }
}

// ================ K7: out_proj (tf32 mma) + LayerNorm + transpose ================
#define K7_AS 68
#define K7_WS 68
__global__ __launch_bounds__(256) void mk_outln(const float* __restrict__ ow,
                                                const float* __restrict__ gam,
                                                const float* __restrict__ bet,
                                                float* __restrict__ out) {
    extern __shared__ unsigned sm_u[];
    unsigned* As = sm_u;
    unsigned* Ws = sm_u + 128 * K7_AS;
    float* Os = (float*)sm_u;
    float* Mu = (float*)(sm_u + 128 * K7_AS + 96 * K7_WS);
    float* Rs = Mu + 128;
    const int l0 = blockIdx.x * 128, b = blockIdx.y, tid = threadIdx.x;

    const int warp = tid >> 5, lane = tid & 31, g = lane >> 2, tg = lane & 3;
    const int wm = (warp & 3) * 32, wn = (warp >> 2) * 48;

    float acc[2][6][4];
    #pragma unroll
    for (int i = 0; i < 2; i++)
        #pragma unroll
        for (int jf = 0; jf < 6; jf++)
            #pragma unroll
            for (int q = 0; q < 4; q++) acc[i][jf][q] = 0.f;

    const float* ysrc = g_zs + ((size_t)b * LQ + l0) * DIQ;
    for (int kc = 0; kc < 3; kc++) {
        int e0 = kc * 64;
        __syncthreads();
        for (int v = tid; v < 128 * 16; v += 256) {
            int l = v >> 4, q = v & 15;
            const float4 f4 = *(const float4*)(ysrc + (size_t)l * DIQ + e0 + q * 4);
            unsigned* dst = &As[l * K7_AS + q * 4];
            dst[0] = f2tf(f4.x); dst[1] = f2tf(f4.y); dst[2] = f2tf(f4.z); dst[3] = f2tf(f4.w);
        }
        for (int v = tid; v < 96 * 16; v += 256) {
            int o = v >> 4, q = v & 15;
            const float4 f4 = *(const float4*)(ow + (size_t)o * DIQ + e0 + q * 4);
            unsigned* dst = &Ws[o * K7_WS + q * 4];
            dst[0] = f2tf(f4.x); dst[1] = f2tf(f4.y); dst[2] = f2tf(f4.z); dst[3] = f2tf(f4.w);
        }
        __syncthreads();
        #pragma unroll
        for (int ks = 0; ks < 8; ks++) {
            int k0 = ks * 8;
            unsigned a[2][4];
            #pragma unroll
            for (int i = 0; i < 2; i++) {
                int m = wm + i * 16;
                a[i][0] = As[(m + g) * K7_AS + k0 + tg];
                a[i][1] = As[(m + g + 8) * K7_AS + k0 + tg];
                a[i][2] = As[(m + g) * K7_AS + k0 + tg + 4];
                a[i][3] = As[(m + g + 8) * K7_AS + k0 + tg + 4];
            }
            #pragma unroll
            for (int jf = 0; jf < 6; jf++) {
                int n = wn + jf * 8 + g;
                unsigned b0 = Ws[n * K7_WS + k0 + tg];
                unsigned b1 = Ws[n * K7_WS + k0 + tg + 4];
                #pragma unroll
                for (int i = 0; i < 2; i++)
                    mma_tf32(acc[i][jf][0], acc[i][jf][1], acc[i][jf][2], acc[i][jf][3],
                             a[i][0], a[i][1], a[i][2], a[i][3], b0, b1);
            }
        }
    }
    __syncthreads();
    #pragma unroll
    for (int i = 0; i < 2; i++)
        #pragma unroll
        for (int jf = 0; jf < 6; jf++) {
            int m = wm + i * 16 + g, n = wn + jf * 8 + tg * 2;
            Os[m * 100 + n]           = acc[i][jf][0];
            Os[m * 100 + n + 1]       = acc[i][jf][1];
            Os[(m + 8) * 100 + n]     = acc[i][jf][2];
            Os[(m + 8) * 100 + n + 1] = acc[i][jf][3];
        }
    __syncthreads();

    if (tid < 128) {
        float s = 0.f;
        for (int o = 0; o < 96; o++) s += Os[tid * 100 + o];
        float mu = s * (1.f / 96.f);
        float v = 0.f;
        for (int o = 0; o < 96; o++) { float d = Os[tid * 100 + o] - mu; v = fmaf(d, d, v); }
        Mu[tid] = mu;
        Rs[tid] = rsqrtf(v * (1.f / 96.f) + 1e-5f);
    }
    __syncthreads();

    float* ob = out + (size_t)b * CQ * LQ + l0;
    for (int idx = tid; idx < 96 * 128; idx += 256) {
        int o = idx >> 7, l = idx & 127;
        ob[(size_t)o * LQ + l] = (Os[l * 100 + o] - Mu[l]) * Rs[l] * gam[o] + bet[o];
    }
}

// ================ launch ================
extern "C" void kernel_launch(void* const* d_in, const int* in_sizes, int n_in,
                              void* d_out, int out_size) {
    const float* x    = (const float*)d_in[0];
    const float* inw  = (const float*)d_in[1];
    const float* cw   = (const float*)d_in[2];
    const float* cb   = (const float*)d_in[3];
    const float* xpw  = (const float*)d_in[4];
    const float* dtw  = (const float*)d_in[5];
    const float* dtb  = (const float*)d_in[6];
    const float* alog = (const float*)d_in[7];
    const float* Dg   = (const float*)d_in[8];
    const float* ow   = (const float*)d_in[9];
    const float* gam  = (const float*)d_in[10];
    const float* bet  = (const float*)d_in[11];
    float* out = (float*)d_out;

    const int SMEM1 = (96 * K1_AS + 128 * K1_WS) * 4;
    const int SMEM3 = (64 * K3_AS + 48 * K3_WS + 64 * 40 + 192 * 6 + 384) * 4;
    const int SMEM7 = (128 * K7_AS + 96 * K7_WS + 256) * 4;

    cudaFuncSetAttribute(mk_inproj, cudaFuncAttributeMaxDynamicSharedMemorySize, SMEM1);
    cudaFuncSetAttribute(mk_xproj,  cudaFuncAttributeMaxDynamicSharedMemorySize, SMEM3);
    cudaFuncSetAttribute(mk_outln,  cudaFuncAttributeMaxDynamicSharedMemorySize, SMEM7);

    mk_inproj<<<dim3(LQ / 128, DIQ / 64, BQ), 256, SMEM1>>>(x, inw);
    mk_conv  <<<dim3(LQ / 32, DIQ / 32, BQ), dim3(32, 8)>>>(cw, cb, alog);
    mk_xproj <<<dim3(LQ / 64, BQ), 256, SMEM3>>>(xpw, dtw, dtb, alog);
    mk_scan  <<<dim3(NCQ, BQ), DIQ>>>(Dg);
    mk_outln <<<dim3(LQ / 128, BQ), 256, SMEM7>>>(ow, gam, bet, out);
}